// round 11
// baseline (speedup 1.0000x reference)
#include <cuda_runtime.h>
#include <cuda_bf16.h>
#include <cstdint>
#include <cstring>

// ---------------- problem constants ----------------
#define FEAT     128
#define NNODES   512
#define BATCH    4
#define NSAMP    5
#define EEDGES   97920
#define OFFBASE  32896
#define NCHUNK   48
#define CHSZ     2040
#define NBS      (BATCH*NSAMP)
#define NVTILES  3568          // valid tiles: 4 * (128*3 + 127*4)
#define NCTA     148

typedef unsigned long long ull;
typedef unsigned int u32;

// ---------------- device scratch ----------------
__device__ float g_projA[BATCH*NNODES*FEAT];
__device__ float g_projB[BATCH*NNODES*FEAT];
__device__ float g_logits[BATCH*EEDGES];
__device__ float g_partZ[NBS*NCHUNK];
__device__ int   g_partE[NBS*NCHUNK];
__device__ __align__(16) unsigned char g_Wimg[65536];  // Whi(32K), Wlo(32K): Wt[n][k] swizzled

// ---------------- smem layout (bytes) ----------------
#define SM_WHI   0
#define SM_WLO   32768
#define SM_AHI   65536
#define SM_ALO   98304
#define SM_AROW  131072   // [2][128] f32
#define SM_B1S   132096
#define SM_G1S   132608
#define SM_BE1S  133120
#define SM_B2S   133632
#define SM_GWS   134144
#define SM_EPI1  134656   // [128] f32
#define SM_EPI2  135168
#define SM_EPIW  135680
#define SM_SCAL  136192
#define SMEM_TOTAL 136224

static __device__ __forceinline__ u32 smem_u32(const void* p) {
    u32 a;
    asm("{ .reg .u64 t; cvta.to.shared.u64 t, %1; cvt.u32.u64 %0, t; }" : "=r"(a) : "l"(p));
    return a;
}

#define LDSM4(r0,r1,r2,r3,addr) \
  asm volatile("ldmatrix.sync.aligned.m8n8.x4.shared.b16 {%0,%1,%2,%3}, [%4];" \
    : "=r"(r0),"=r"(r1),"=r"(r2),"=r"(r3) : "r"(addr))

#define MMA16816(d, a0,a1,a2,a3, b0,b1) \
  asm volatile("mma.sync.aligned.m16n8k16.row.col.f32.bf16.bf16.f32 " \
    "{%0,%1,%2,%3}, {%4,%5,%6,%7}, {%8,%9}, {%0,%1,%2,%3};" \
    : "+f"((d)[0]),"+f"((d)[1]),"+f"((d)[2]),"+f"((d)[3]) \
    : "r"(a0),"r"(a1),"r"(a2),"r"(a3), "r"(b0),"r"(b1))

// ---------------- Threefry / gumbel ----------------
#define TF_ROUND(r) { x0 += x1; x1 = (x1 << (r)) | (x1 >> (32 - (r))); x1 ^= x0; }
static __device__ __forceinline__ u32 tf_xor(u32 x0, u32 x1) {
    const u32 k0 = 0u, k1 = 42u;
    const u32 ks2 = 0x1BD11BDAu ^ k0 ^ k1;
    x0 += k0; x1 += k1;
    TF_ROUND(13) TF_ROUND(15) TF_ROUND(26) TF_ROUND(6)
    x0 += k1; x1 += ks2 + 1u;
    TF_ROUND(17) TF_ROUND(29) TF_ROUND(16) TF_ROUND(24)
    x0 += ks2; x1 += k0 + 2u;
    TF_ROUND(13) TF_ROUND(15) TF_ROUND(26) TF_ROUND(6)
    x0 += k0; x1 += k1 + 3u;
    TF_ROUND(17) TF_ROUND(29) TF_ROUND(16) TF_ROUND(24)
    x0 += k1; x1 += ks2 + 4u;
    TF_ROUND(13) TF_ROUND(15) TF_ROUND(26) TF_ROUND(6)
    x0 += ks2; x1 += k0 + 5u;
    return x0 ^ x1;
}
static __device__ __forceinline__ float bits_to_gumbel(u32 bits) {
    float f = __uint_as_float((bits >> 9) | 0x3f800000u) - 1.0f;
    float u = fmaxf(f, 1.17549435e-38f);
    return -logf(-logf(u));
}

// valid-tile decode: per batch 892 tiles (r 257..384: 3 chunks, r 385..511: 4)
static __device__ __forceinline__ void tile_decode(int t, int& b, int& r, int& c) {
    b = t / 892;
    int idx = t - b * 892;
    if (idx < 384) { int d = idx / 3; r = 257 + d; c = idx - d * 3; }
    else { int i2 = idx - 384; r = 385 + (i2 >> 2); c = i2 & 3; }
}

// ---------------- K1: per-node projections ----------------------------------
__global__ void k_proj(const float* __restrict__ nodes, const float* __restrict__ W1) {
    __shared__ float nrow[4][FEAT];
    const int tid = threadIdx.x, blk = blockIdx.x;
    const float* src = nodes + (size_t)blk * 4 * FEAT;
    for (int i = tid; i < 4 * FEAT; i += 256) ((float*)nrow)[i] = src[i];
    __syncthreads();
    const int half = tid >> 7, o = tid & 127;
    const float* w = W1 + half * FEAT * FEAT + o;
    float a0 = 0.f, a1 = 0.f, a2 = 0.f, a3 = 0.f;
#pragma unroll 8
    for (int k = 0; k < FEAT; k++) {
        float wv = w[k * FEAT];
        a0 = fmaf(nrow[0][k], wv, a0);
        a1 = fmaf(nrow[1][k], wv, a1);
        a2 = fmaf(nrow[2][k], wv, a2);
        a3 = fmaf(nrow[3][k], wv, a3);
    }
    float* dst = half ? g_projB : g_projA;
    int base = blk * 4 * FEAT + o;
    dst[base] = a0; dst[base + FEAT] = a1;
    dst[base + 2 * FEAT] = a2; dst[base + 3 * FEAT] = a3;
}

// ---------------- K1b: W2 -> bf16 hi/lo Wt[n][k] swizzled image --------------
__global__ void k_wprep(const float* __restrict__ W2) {
    const int idx = blockIdx.x * 256 + threadIdx.x;   // 0..16383
    const int k = idx >> 7, n = idx & 127;
    const float w = W2[k * FEAT + n];
    __nv_bfloat16 hb = __float2bfloat16(w);
    float lo = w - __bfloat162float(hb);
    __nv_bfloat16 lb = __float2bfloat16(lo);
    const u32 off = (u32)(n * 256) + (((u32)(k * 2)) ^ ((u32)(n & 7) << 4));
    unsigned short hbits, lbits;
    memcpy(&hbits, &hb, 2); memcpy(&lbits, &lb, 2);
    *(unsigned short*)(g_Wimg + off) = hbits;
    *(unsigned short*)(g_Wimg + 32768 + off) = lbits;
}

// ---------------- K2: persistent mma.sync edge-MLP (512 thr, no spills) ------
__global__ void __launch_bounds__(512, 1)
k_edge_mma(const float* __restrict__ b1, const float* __restrict__ g1,
           const float* __restrict__ be1, const float* __restrict__ b2,
           const float* __restrict__ g2, const float* __restrict__ be2,
           const float* __restrict__ W3) {
    extern __shared__ __align__(1024) char smem[];
    const u32 sb = smem_u32(smem);
    float* smf = (float*)smem;
    const int tid = threadIdx.x;
    const int lane = tid & 31, w = tid >> 5;

    // ---- one-time init ----
    {
        const uint4* src = (const uint4*)g_Wimg;
        uint4* dst = (uint4*)smem;
        for (int i = tid; i < 4096; i += 512) dst[i] = src[i];
    }
    if (tid < 128) {
        smf[SM_B1S/4 + tid]  = b1[tid];
        smf[SM_G1S/4 + tid]  = g1[tid];
        smf[SM_BE1S/4 + tid] = be1[tid];
        smf[SM_B2S/4 + tid]  = b2[tid];
        smf[SM_GWS/4 + tid]  = g2[tid] * W3[tid];
    }
    __syncthreads();
    if (tid == 0) {
        float sg = 0.f, sbw = 0.f;
        for (int j = 0; j < 128; j++) {
            sg  += smf[SM_GWS/4 + j];
            sbw += be2[j] * W3[j];
        }
        smf[SM_SCAL/4 + 0] = sg;
        smf[SM_SCAL/4 + 1] = sbw;
    }
    __syncthreads();

    const float* g1s  = smf + SM_G1S/4;
    const float* be1s = smf + SM_BE1S/4;
    float* arow = smf + SM_AROW/4;     // [2][128]
    float* epi1 = smf + SM_EPI1/4;
    float* epi2 = smf + SM_EPI2/4;
    float* epiw = smf + SM_EPIW/4;

    // phase-1 geometry: thread = (row m, quarter q); q-threads are same-warp lanes
    const int m = tid >> 2, q = tid & 3;
    const u32 mswz = (u32)(m & 7) << 4;

    // GEMM geometry: 16 warps = 8 M-warps x 2 N-halves
    const int wm = w & 7, nhalf = w >> 3;
    const u32 swz = (u32)(lane & 7) << 4;
    const u32 a_rowoff = (u32)(16*wm + (lane & 7) + ((lane >> 3) & 1) * 8) * 256;
    const u32 akc = (u32)((lane >> 4) & 1) * 16;
    const u32 b_rowin = (u32)(((lane >> 4) & 1) * 8 + (lane & 7)) * 256 + (u32)nhalf * 16384;
    const u32 bkc = (u32)((lane >> 3) & 1) * 16;
    const u32 aHIb = sb + SM_AHI + a_rowoff;
    const u32 aLOb = sb + SM_ALO + a_rowoff;
    const u32 wHIb = sb + SM_WHI + b_rowin;
    const u32 wLOb = sb + SM_WLO + b_rowin;

    // ---- initial arow prefetch (tile t0) ----
    int t = blockIdx.x;
    {
        int b_, r_, c_; tile_decode(t, b_, r_, c_);
        if (tid < 128)
            arow[tid] = g_projA[(((size_t)(b_ << 9) + r_) << 7) + tid] + smf[SM_B1S/4 + tid];
    }
    __syncthreads();

    int pc = 0;
    for (; t < NVTILES; t += NCTA, pc++) {
        int b_, r_, c_; tile_decode(t, b_, r_, c_);
        const int src0 = c_ << 7;
        const int nvalid = min(128, r_ - src0);
        const int par = pc & 1;
        const float* ar = arow + par * 128 + q * 32;

        // ---- phase 1: direct loads, relu + LN stats ----
        const bool valid = m < nvalid;
        float x[32];
        float S1p = 0.f, S2p = 0.f;
        if (valid) {
            const float4* bp = (const float4*)(g_projB + (((size_t)(b_ << 9) + src0 + m) << 7) + q * 32);
#pragma unroll
            for (int i = 0; i < 8; i++) {
                float4 v4 = bp[i];
                const int j0 = i * 4;
                x[j0+0] = fmaxf(ar[j0+0] + v4.x, 0.f);
                x[j0+1] = fmaxf(ar[j0+1] + v4.y, 0.f);
                x[j0+2] = fmaxf(ar[j0+2] + v4.z, 0.f);
                x[j0+3] = fmaxf(ar[j0+3] + v4.w, 0.f);
                S1p += x[j0+0] + x[j0+1] + x[j0+2] + x[j0+3];
                S2p = fmaf(x[j0+0], x[j0+0], S2p); S2p = fmaf(x[j0+1], x[j0+1], S2p);
                S2p = fmaf(x[j0+2], x[j0+2], S2p); S2p = fmaf(x[j0+3], x[j0+3], S2p);
            }
        } else {
#pragma unroll
            for (int i = 0; i < 32; i++) x[i] = 0.f;
        }
        // reduce stats across the 4 quarter-lanes (same warp)
        S1p += __shfl_xor_sync(0xffffffffu, S1p, 1);
        S1p += __shfl_xor_sync(0xffffffffu, S1p, 2);
        S2p += __shfl_xor_sync(0xffffffffu, S2p, 1);
        S2p += __shfl_xor_sync(0xffffffffu, S2p, 2);
        const float mu = S1p * (1.f/128.f);
        const float var = S2p * (1.f/128.f) - mu * mu;
        const float rstd = rsqrtf(var + 1e-5f);

        // convert + store A tiles (hi/lo)
#pragma unroll
        for (int i = 0; i < 4; i++) {
            u32 hu[4], lu[4];
#pragma unroll
            for (int pp = 0; pp < 4; pp++) {
                const int jl = i*8 + pp*2;
                const int j  = q*32 + jl;
                float y0 = 0.f, y1 = 0.f;
                if (valid) {
                    y0 = fmaf((x[jl]   - mu) * rstd, g1s[j],   be1s[j]);
                    y1 = fmaf((x[jl+1] - mu) * rstd, g1s[j+1], be1s[j+1]);
                }
                __nv_bfloat162 hb = __floats2bfloat162_rn(y0, y1);
                float r0 = y0 - __bfloat162float(hb.x);
                float r1 = y1 - __bfloat162float(hb.y);
                __nv_bfloat162 lb = __floats2bfloat162_rn(r0, r1);
                memcpy(&hu[pp], &hb, 4); memcpy(&lu[pp], &lb, 4);
            }
            const u32 off = (u32)(m * 256) + (((u32)(q*64 + i*16)) ^ mswz);
            *(uint4*)(smem + SM_AHI + off) = make_uint4(hu[0], hu[1], hu[2], hu[3]);
            *(uint4*)(smem + SM_ALO + off) = make_uint4(lu[0], lu[1], lu[2], lu[3]);
        }

        // ---- prefetch next tile's arow (overlaps with GEMM) ----
        {
            const int tn = t + NCTA;
            if (tn < NVTILES && tid < 128) {
                int bn, rn, cn; tile_decode(tn, bn, rn, cn);
                arow[(par ^ 1) * 128 + tid] =
                    g_projA[(((size_t)(bn << 9) + rn) << 7) + tid] + smf[SM_B1S/4 + tid];
            }
        }
        __syncthreads();   // A tiles ready

        // ---- GEMM: D = Ahi*Whi + Alo*Whi + Ahi*Wlo ----
        float acc[32];
#pragma unroll
        for (int i = 0; i < 32; i++) acc[i] = 0.f;

#pragma unroll
        for (int s = 0; s < 8; s++) {
            const u32 aoff = ((u32)(s*32) + akc) ^ swz;
            const u32 boff = ((u32)(s*32) + bkc) ^ swz;
            u32 ah0,ah1,ah2,ah3, al0,al1,al2,al3;
            LDSM4(ah0,ah1,ah2,ah3, aHIb + aoff);
            LDSM4(al0,al1,al2,al3, aLOb + aoff);
#pragma unroll
            for (int u = 0; u < 4; u++) {
                u32 bh0,bh1,bh2,bh3, bl0,bl1,bl2,bl3;
                LDSM4(bh0,bh1,bh2,bh3, wHIb + (u32)(u*4096) + boff);
                LDSM4(bl0,bl1,bl2,bl3, wLOb + (u32)(u*4096) + boff);
                MMA16816(acc + u*8,     ah0,ah1,ah2,ah3, bh0,bh1);
                MMA16816(acc + u*8 + 4, ah0,ah1,ah2,ah3, bh2,bh3);
                MMA16816(acc + u*8,     al0,al1,al2,al3, bh0,bh1);
                MMA16816(acc + u*8 + 4, al0,al1,al2,al3, bh2,bh3);
                MMA16816(acc + u*8,     ah0,ah1,ah2,ah3, bl0,bl1);
                MMA16816(acc + u*8 + 4, ah0,ah1,ah2,ah3, bl2,bl3);
            }
        }

        // ---- epilogue: relu + LN stats + W3 dot (per N-half, then combine) ----
        float S1a=0.f,S2a=0.f,Swa=0.f, S1b=0.f,S2b=0.f,Swb=0.f;
        const int tq = (lane & 3) * 2;
        const int nb = nhalf * 64;
#pragma unroll
        for (int u = 0; u < 4; u++) {
            const int j1 = nb + u*16 + tq;
            const int j2 = j1 + 8;
            float2 b2p1 = *(float2*)(smem + SM_B2S + j1*4);
            float2 gwp1 = *(float2*)(smem + SM_GWS + j1*4);
            float2 b2p2 = *(float2*)(smem + SM_B2S + j2*4);
            float2 gwp2 = *(float2*)(smem + SM_GWS + j2*4);
            float v0 = fmaxf(acc[u*8+0] + b2p1.x, 0.f);
            float v1 = fmaxf(acc[u*8+1] + b2p1.y, 0.f);
            float v2 = fmaxf(acc[u*8+2] + b2p1.x, 0.f);
            float v3 = fmaxf(acc[u*8+3] + b2p1.y, 0.f);
            float v4 = fmaxf(acc[u*8+4] + b2p2.x, 0.f);
            float v5 = fmaxf(acc[u*8+5] + b2p2.y, 0.f);
            float v6 = fmaxf(acc[u*8+6] + b2p2.x, 0.f);
            float v7 = fmaxf(acc[u*8+7] + b2p2.y, 0.f);
            S1a += v0+v1+v4+v5;
            S2a = fmaf(v0,v0,fmaf(v1,v1,fmaf(v4,v4,fmaf(v5,v5,S2a))));
            Swa = fmaf(gwp1.x,v0,fmaf(gwp1.y,v1,fmaf(gwp2.x,v4,fmaf(gwp2.y,v5,Swa))));
            S1b += v2+v3+v6+v7;
            S2b = fmaf(v2,v2,fmaf(v3,v3,fmaf(v6,v6,fmaf(v7,v7,S2b))));
            Swb = fmaf(gwp1.x,v2,fmaf(gwp1.y,v3,fmaf(gwp2.x,v6,fmaf(gwp2.y,v7,Swb))));
        }
#pragma unroll
        for (int o = 1; o <= 2; o <<= 1) {
            S1a += __shfl_xor_sync(0xffffffffu, S1a, o);
            S2a += __shfl_xor_sync(0xffffffffu, S2a, o);
            Swa += __shfl_xor_sync(0xffffffffu, Swa, o);
            S1b += __shfl_xor_sync(0xffffffffu, S1b, o);
            S2b += __shfl_xor_sync(0xffffffffu, S2b, o);
            Swb += __shfl_xor_sync(0xffffffffu, Swb, o);
        }
        const int rA = 16*wm + (lane >> 2);
        if ((lane & 3) == 0 && nhalf == 1) {
            epi1[rA] = S1a; epi2[rA] = S2a; epiw[rA] = Swa;
            epi1[rA+8] = S1b; epi2[rA+8] = S2b; epiw[rA+8] = Swb;
        }
        __syncthreads();   // also the iteration barrier
        if ((lane & 3) == 0 && nhalf == 0) {
            const float Sgw = smf[SM_SCAL/4 + 0], Sbw = smf[SM_SCAL/4 + 1];
            const int offr = (r_ * (r_ - 1)) / 2 - OFFBASE + src0;
            {
                const float S1t = S1a + epi1[rA];
                const float S2t = S2a + epi2[rA];
                const float Swt = Swa + epiw[rA];
                const float mu2 = S1t * (1.f/128.f);
                const float var2 = S2t * (1.f/128.f) - mu2 * mu2;
                const float rs2 = rsqrtf(var2 + 1e-5f);
                if (rA < nvalid)
                    g_logits[b_ * EEDGES + offr + rA] = rs2 * (Swt - mu2 * Sgw) + Sbw;
            }
            {
                const int rB = rA + 8;
                const float S1t = S1b + epi1[rB];
                const float S2t = S2b + epi2[rB];
                const float Swt = Swb + epiw[rB];
                const float mu2 = S1t * (1.f/128.f);
                const float var2 = S2t * (1.f/128.f) - mu2 * mu2;
                const float rs2 = rsqrtf(var2 + 1e-5f);
                if (rB < nvalid)
                    g_logits[b_ * EEDGES + offr + rB] = rs2 * (Swt - mu2 * Sgw) + Sbw;
            }
        }
    }
}

// ---------------- K3a: gumbel + partial argmax ------------------------------
__global__ void k_gumbel_part() {
    const int c = blockIdx.x;
    const int bs = blockIdx.y;
    const int b = bs / NSAMP;
    const int tid = threadIdx.x;
    const float* lg = g_logits + b * EEDGES;

    float bz = __int_as_float(0xff800000);
    int bestE = 0x7fffffff;

    for (int t = tid; t < CHSZ; t += 256) {
        const u32 e = (u32)(c * CHSZ + t);
        const u32 i = (u32)bs * (u32)EEDGES + e;
        float z = lg[e] + bits_to_gumbel(tf_xor(0u, i));
        if (z > bz || (z == bz && (int)e < bestE)) { bz = z; bestE = (int)e; }
    }

    __shared__ float zs[256];
    __shared__ int   es[256];
    zs[tid] = bz; es[tid] = bestE;
    __syncthreads();
    for (int st = 128; st; st >>= 1) {
        if (tid < st) {
            if (zs[tid + st] > zs[tid] ||
                (zs[tid + st] == zs[tid] && es[tid + st] < es[tid])) {
                zs[tid] = zs[tid + st]; es[tid] = es[tid + st];
            }
        }
        __syncthreads();
    }
    if (tid == 0) { g_partZ[bs * NCHUNK + c] = zs[0]; g_partE[bs * NCHUNK + c] = es[0]; }
}

// ---------------- K3b+K4: final argmax + scatter -----------------------------
__global__ void k_final_scatter(float* __restrict__ out) {
    const int t = threadIdx.x;
    if (t >= NBS) return;
    float bz = __int_as_float(0xff800000);
    int bestE = 0;
    for (int c = 0; c < NCHUNK; c++) {
        float z = g_partZ[t * NCHUNK + c];
        int   e = g_partE[t * NCHUNK + c];
        if (z > bz || (z == bz && e < bestE)) { bz = z; bestE = e; }
    }
    const int v = bestE + OFFBASE;
    int r = (int)((1.0 + sqrt(8.0 * (double)v + 1.0)) * 0.5);
    while (r * (r - 1) / 2 > v) r--;
    while (r * (r + 1) / 2 <= v) r++;
    const int src = v - r * (r - 1) / 2;
    const int b = t / NSAMP;
    out[(size_t)b * NNODES * NNODES + r * NNODES + src] = 1.0f;
}

// ---------------- launch -----------------------------------------------------
extern "C" void kernel_launch(void* const* d_in, const int* in_sizes, int n_in,
                              void* d_out, int out_size) {
    const float* nodes = (const float*)d_in[0];
    const float* W1  = (const float*)d_in[1];
    const float* b1  = (const float*)d_in[2];
    const float* g1  = (const float*)d_in[3];
    const float* be1 = (const float*)d_in[4];
    const float* W2  = (const float*)d_in[5];
    const float* b2  = (const float*)d_in[6];
    const float* g2  = (const float*)d_in[7];
    const float* be2 = (const float*)d_in[8];
    const float* W3  = (const float*)d_in[9];
    float* out = (float*)d_out;

    cudaMemsetAsync(out, 0, (size_t)out_size * sizeof(float), 0);

    k_proj<<<(BATCH * NNODES) / 4, 256>>>(nodes, W1);
    k_wprep<<<64, 256>>>(W2);

    cudaFuncSetAttribute(k_edge_mma, cudaFuncAttributeMaxDynamicSharedMemorySize,
                         SMEM_TOTAL);
    k_edge_mma<<<NCTA, 512, SMEM_TOTAL>>>(b1, g1, be1, b2, g2, be2, W3);

    dim3 gg(NCHUNK, NBS);
    k_gumbel_part<<<gg, 256>>>();
    k_final_scatter<<<1, 32>>>(out);
}

// round 12
// speedup vs baseline: 1.1095x; 1.1095x over previous
#include <cuda_runtime.h>
#include <cuda_bf16.h>
#include <cstdint>
#include <cstring>

// ---------------- problem constants ----------------
#define FEAT     128
#define NNODES   512
#define BATCH    4
#define NSAMP    5
#define EEDGES   97920
#define OFFBASE  32896
#define NCHUNK   48
#define CHSZ     2040
#define NBS      (BATCH*NSAMP)
#define NT_B     1656          // valid M=64 tiles per batch
#define NVTILES  (4*NT_B)      // 6624
#define NCTA     296

typedef unsigned long long ull;
typedef unsigned int u32;

// ---------------- device scratch ----------------
__device__ float g_projA[BATCH*NNODES*FEAT];
__device__ float g_projB[BATCH*NNODES*FEAT];
__device__ float g_logits[BATCH*EEDGES];
__device__ float g_partZ[NBS*NCHUNK];
__device__ int   g_partE[NBS*NCHUNK];
__device__ __align__(16) unsigned char g_Wimg[65536];  // Whi(32K), Wlo(32K): Wt[n][k] swizzled

// ---------------- smem layout (bytes) ----------------
#define SM_WHI   0        // 32768
#define SM_WLO   32768    // 32768
#define SM_AHI   65536    // 16384 (64 rows x 256B)
#define SM_ALO   81920    // 16384
#define SM_AROW  98304    // [2][128] f32
#define SM_B1S   99328
#define SM_G1S   99840
#define SM_BE1S  100352
#define SM_B2S   100864
#define SM_GWS   101376
#define SM_EPI1  101888   // [64] f32
#define SM_EPI2  102144
#define SM_EPIW  102400
#define SM_SCAL  102656
#define SMEM_TOTAL 102688

static __device__ __forceinline__ u32 smem_u32(const void* p) {
    u32 a;
    asm("{ .reg .u64 t; cvta.to.shared.u64 t, %1; cvt.u32.u64 %0, t; }" : "=r"(a) : "l"(p));
    return a;
}

#define LDSM4(r0,r1,r2,r3,addr) \
  asm volatile("ldmatrix.sync.aligned.m8n8.x4.shared.b16 {%0,%1,%2,%3}, [%4];" \
    : "=r"(r0),"=r"(r1),"=r"(r2),"=r"(r3) : "r"(addr))

#define MMA16816(d, a0,a1,a2,a3, b0,b1) \
  asm volatile("mma.sync.aligned.m16n8k16.row.col.f32.bf16.bf16.f32 " \
    "{%0,%1,%2,%3}, {%4,%5,%6,%7}, {%8,%9}, {%0,%1,%2,%3};" \
    : "+f"((d)[0]),"+f"((d)[1]),"+f"((d)[2]),"+f"((d)[3]) \
    : "r"(a0),"r"(a1),"r"(a2),"r"(a3), "r"(b0),"r"(b1))

// ---------------- Threefry / gumbel ----------------
#define TF_ROUND(r) { x0 += x1; x1 = (x1 << (r)) | (x1 >> (32 - (r))); x1 ^= x0; }
static __device__ __forceinline__ u32 tf_xor(u32 x0, u32 x1) {
    const u32 k0 = 0u, k1 = 42u;
    const u32 ks2 = 0x1BD11BDAu ^ k0 ^ k1;
    x0 += k0; x1 += k1;
    TF_ROUND(13) TF_ROUND(15) TF_ROUND(26) TF_ROUND(6)
    x0 += k1; x1 += ks2 + 1u;
    TF_ROUND(17) TF_ROUND(29) TF_ROUND(16) TF_ROUND(24)
    x0 += ks2; x1 += k0 + 2u;
    TF_ROUND(13) TF_ROUND(15) TF_ROUND(26) TF_ROUND(6)
    x0 += k0; x1 += k1 + 3u;
    TF_ROUND(17) TF_ROUND(29) TF_ROUND(16) TF_ROUND(24)
    x0 += k1; x1 += ks2 + 4u;
    TF_ROUND(13) TF_ROUND(15) TF_ROUND(26) TF_ROUND(6)
    x0 += ks2; x1 += k0 + 5u;
    return x0 ^ x1;
}
static __device__ __forceinline__ float bits_to_gumbel(u32 bits) {
    float f = __uint_as_float((bits >> 9) | 0x3f800000u) - 1.0f;
    float u = fmaxf(f, 1.17549435e-38f);
    return -logf(-logf(u));
}

// valid-tile decode for M=64 chunks.
// per batch: r 257..320 -> 5 chunks, 321..384 -> 6, 385..448 -> 7, 449..511 -> 8
static __device__ __forceinline__ void tile_decode(int t, int& b, int& r, int& c) {
    b = t / NT_B;
    int idx = t - b * NT_B;
    if (idx < 320)       { int d = idx / 5;            r = 257 + d; c = idx - d * 5; }
    else if (idx < 704)  { int i = idx - 320; int d = i / 6; r = 321 + d; c = i - d * 6; }
    else if (idx < 1152) { int i = idx - 704; int d = i / 7; r = 385 + d; c = i - d * 7; }
    else                 { int i = idx - 1152; int d = i >> 3; r = 449 + d; c = i & 7; }
}

// ---------------- K1: per-node projections ----------------------------------
__global__ void k_proj(const float* __restrict__ nodes, const float* __restrict__ W1) {
    __shared__ float nrow[4][FEAT];
    const int tid = threadIdx.x, blk = blockIdx.x;
    const float* src = nodes + (size_t)blk * 4 * FEAT;
    for (int i = tid; i < 4 * FEAT; i += 256) ((float*)nrow)[i] = src[i];
    __syncthreads();
    const int half = tid >> 7, o = tid & 127;
    const float* w = W1 + half * FEAT * FEAT + o;
    float a0 = 0.f, a1 = 0.f, a2 = 0.f, a3 = 0.f;
#pragma unroll 8
    for (int k = 0; k < FEAT; k++) {
        float wv = w[k * FEAT];
        a0 = fmaf(nrow[0][k], wv, a0);
        a1 = fmaf(nrow[1][k], wv, a1);
        a2 = fmaf(nrow[2][k], wv, a2);
        a3 = fmaf(nrow[3][k], wv, a3);
    }
    float* dst = half ? g_projB : g_projA;
    int base = blk * 4 * FEAT + o;
    dst[base] = a0; dst[base + FEAT] = a1;
    dst[base + 2 * FEAT] = a2; dst[base + 3 * FEAT] = a3;
}

// ---------------- K1b: W2 -> bf16 hi/lo Wt[n][k] swizzled image --------------
__global__ void k_wprep(const float* __restrict__ W2) {
    const int idx = blockIdx.x * 256 + threadIdx.x;   // 0..16383
    const int k = idx >> 7, n = idx & 127;
    const float w = W2[k * FEAT + n];
    __nv_bfloat16 hb = __float2bfloat16(w);
    float lo = w - __bfloat162float(hb);
    __nv_bfloat16 lb = __float2bfloat16(lo);
    const u32 off = (u32)(n * 256) + (((u32)(k * 2)) ^ ((u32)(n & 7) << 4));
    unsigned short hbits, lbits;
    memcpy(&hbits, &hb, 2); memcpy(&lbits, &lb, 2);
    *(unsigned short*)(g_Wimg + off) = hbits;
    *(unsigned short*)(g_Wimg + 32768 + off) = lbits;
}

// ---------------- K2: persistent mma.sync edge-MLP (M=64, 2 CTA/SM) ----------
__global__ void __launch_bounds__(256, 2)
k_edge_mma(const float* __restrict__ b1, const float* __restrict__ g1,
           const float* __restrict__ be1, const float* __restrict__ b2,
           const float* __restrict__ g2, const float* __restrict__ be2,
           const float* __restrict__ W3) {
    extern __shared__ __align__(1024) char smem[];
    const u32 sb = smem_u32(smem);
    float* smf = (float*)smem;
    const int tid = threadIdx.x;
    const int lane = tid & 31, w = tid >> 5;

    // ---- one-time init ----
    {
        const uint4* src = (const uint4*)g_Wimg;
        uint4* dst = (uint4*)smem;
        for (int i = tid; i < 4096; i += 256) dst[i] = src[i];
    }
    if (tid < 128) {
        smf[SM_B1S/4 + tid]  = b1[tid];
        smf[SM_G1S/4 + tid]  = g1[tid];
        smf[SM_BE1S/4 + tid] = be1[tid];
        smf[SM_B2S/4 + tid]  = b2[tid];
        smf[SM_GWS/4 + tid]  = g2[tid] * W3[tid];
    }
    __syncthreads();
    if (tid == 0) {
        float sg = 0.f, sbw = 0.f;
        for (int j = 0; j < 128; j++) {
            sg  += smf[SM_GWS/4 + j];
            sbw += be2[j] * W3[j];
        }
        smf[SM_SCAL/4 + 0] = sg;
        smf[SM_SCAL/4 + 1] = sbw;
    }
    __syncthreads();

    const float* g1s  = smf + SM_G1S/4;
    const float* be1s = smf + SM_BE1S/4;
    float* arow = smf + SM_AROW/4;     // [2][128]
    float* epi1 = smf + SM_EPI1/4;
    float* epi2 = smf + SM_EPI2/4;
    float* epiw = smf + SM_EPIW/4;

    // phase-1 geometry: thread = (row m 0..63, quarter q); q-lanes adjacent in warp
    const int m = tid >> 2, q = tid & 3;
    const u32 mswz = (u32)(m & 7) << 4;

    // GEMM geometry: 8 warps = 4 M-warps x 2 N-halves
    const int wm = w & 3, nhalf = w >> 2;
    const u32 swz = (u32)(lane & 7) << 4;
    const u32 a_rowoff = (u32)(16*wm + (lane & 7) + ((lane >> 3) & 1) * 8) * 256;
    const u32 akc = (u32)((lane >> 4) & 1) * 16;
    const u32 b_rowin = (u32)(((lane >> 4) & 1) * 8 + (lane & 7)) * 256 + (u32)nhalf * 16384;
    const u32 bkc = (u32)((lane >> 3) & 1) * 16;
    const u32 aHIb = sb + SM_AHI + a_rowoff;
    const u32 aLOb = sb + SM_ALO + a_rowoff;
    const u32 wHIb = sb + SM_WHI + b_rowin;
    const u32 wLOb = sb + SM_WLO + b_rowin;

    // ---- initial arow prefetch (tile t0) ----
    int t = blockIdx.x;
    if (t < NVTILES) {
        int b_, r_, c_; tile_decode(t, b_, r_, c_);
        if (tid < 128)
            arow[tid] = g_projA[(((size_t)(b_ << 9) + r_) << 7) + tid] + smf[SM_B1S/4 + tid];
    }
    __syncthreads();

    int pc = 0;
    for (; t < NVTILES; t += NCTA, pc++) {
        int b_, r_, c_; tile_decode(t, b_, r_, c_);
        const int src0 = c_ << 6;
        const int nvalid = min(64, r_ - src0);
        const int par = pc & 1;
        const float* ar = arow + par * 128 + q * 32;

        // ---- phase 1: direct loads, relu + LN stats ----
        const bool valid = m < nvalid;
        float x[32];
        float S1p = 0.f, S2p = 0.f;
        if (valid) {
            const float4* bp = (const float4*)(g_projB + (((size_t)(b_ << 9) + src0 + m) << 7) + q * 32);
#pragma unroll
            for (int i = 0; i < 8; i++) {
                float4 v4 = bp[i];
                const int j0 = i * 4;
                x[j0+0] = fmaxf(ar[j0+0] + v4.x, 0.f);
                x[j0+1] = fmaxf(ar[j0+1] + v4.y, 0.f);
                x[j0+2] = fmaxf(ar[j0+2] + v4.z, 0.f);
                x[j0+3] = fmaxf(ar[j0+3] + v4.w, 0.f);
                S1p += x[j0+0] + x[j0+1] + x[j0+2] + x[j0+3];
                S2p = fmaf(x[j0+0], x[j0+0], S2p); S2p = fmaf(x[j0+1], x[j0+1], S2p);
                S2p = fmaf(x[j0+2], x[j0+2], S2p); S2p = fmaf(x[j0+3], x[j0+3], S2p);
            }
        } else {
#pragma unroll
            for (int i = 0; i < 32; i++) x[i] = 0.f;
        }
        S1p += __shfl_xor_sync(0xffffffffu, S1p, 1);
        S1p += __shfl_xor_sync(0xffffffffu, S1p, 2);
        S2p += __shfl_xor_sync(0xffffffffu, S2p, 1);
        S2p += __shfl_xor_sync(0xffffffffu, S2p, 2);
        const float mu = S1p * (1.f/128.f);
        const float var = S2p * (1.f/128.f) - mu * mu;
        const float rstd = rsqrtf(var + 1e-5f);

        // convert + store A tiles (hi/lo)
#pragma unroll
        for (int i = 0; i < 4; i++) {
            u32 hu[4], lu[4];
#pragma unroll
            for (int pp = 0; pp < 4; pp++) {
                const int jl = i*8 + pp*2;
                const int j  = q*32 + jl;
                float y0 = 0.f, y1 = 0.f;
                if (valid) {
                    y0 = fmaf((x[jl]   - mu) * rstd, g1s[j],   be1s[j]);
                    y1 = fmaf((x[jl+1] - mu) * rstd, g1s[j+1], be1s[j+1]);
                }
                __nv_bfloat162 hb = __floats2bfloat162_rn(y0, y1);
                float r0 = y0 - __bfloat162float(hb.x);
                float r1 = y1 - __bfloat162float(hb.y);
                __nv_bfloat162 lb = __floats2bfloat162_rn(r0, r1);
                memcpy(&hu[pp], &hb, 4); memcpy(&lu[pp], &lb, 4);
            }
            const u32 off = (u32)(m * 256) + (((u32)(q*64 + i*16)) ^ mswz);
            *(uint4*)(smem + SM_AHI + off) = make_uint4(hu[0], hu[1], hu[2], hu[3]);
            *(uint4*)(smem + SM_ALO + off) = make_uint4(lu[0], lu[1], lu[2], lu[3]);
        }

        // ---- prefetch next tile's arow (overlaps with GEMM) ----
        {
            const int tn = t + NCTA;
            if (tn < NVTILES && tid < 128) {
                int bn, rn, cn; tile_decode(tn, bn, rn, cn);
                arow[(par ^ 1) * 128 + tid] =
                    g_projA[(((size_t)(bn << 9) + rn) << 7) + tid] + smf[SM_B1S/4 + tid];
            }
        }
        __syncthreads();   // A tiles ready

        // ---- GEMM: D = Ahi*Whi + Alo*Whi + Ahi*Wlo ----
        float acc[32];
#pragma unroll
        for (int i = 0; i < 32; i++) acc[i] = 0.f;

#pragma unroll
        for (int s = 0; s < 8; s++) {
            const u32 aoff = ((u32)(s*32) + akc) ^ swz;
            const u32 boff = ((u32)(s*32) + bkc) ^ swz;
            u32 ah0,ah1,ah2,ah3, al0,al1,al2,al3;
            LDSM4(ah0,ah1,ah2,ah3, aHIb + aoff);
            LDSM4(al0,al1,al2,al3, aLOb + aoff);
#pragma unroll
            for (int u = 0; u < 4; u++) {
                u32 bh0,bh1,bh2,bh3, bl0,bl1,bl2,bl3;
                LDSM4(bh0,bh1,bh2,bh3, wHIb + (u32)(u*4096) + boff);
                LDSM4(bl0,bl1,bl2,bl3, wLOb + (u32)(u*4096) + boff);
                MMA16816(acc + u*8,     ah0,ah1,ah2,ah3, bh0,bh1);
                MMA16816(acc + u*8 + 4, ah0,ah1,ah2,ah3, bh2,bh3);
                MMA16816(acc + u*8,     al0,al1,al2,al3, bh0,bh1);
                MMA16816(acc + u*8 + 4, al0,al1,al2,al3, bh2,bh3);
                MMA16816(acc + u*8,     ah0,ah1,ah2,ah3, bl0,bl1);
                MMA16816(acc + u*8 + 4, ah0,ah1,ah2,ah3, bl2,bl3);
            }
        }

        // ---- epilogue: relu + LN stats + W3 dot (per N-half, then combine) ----
        float S1a=0.f,S2a=0.f,Swa=0.f, S1b=0.f,S2b=0.f,Swb=0.f;
        const int tq = (lane & 3) * 2;
        const int nb = nhalf * 64;
#pragma unroll
        for (int u = 0; u < 4; u++) {
            const int j1 = nb + u*16 + tq;
            const int j2 = j1 + 8;
            float2 b2p1 = *(float2*)(smem + SM_B2S + j1*4);
            float2 gwp1 = *(float2*)(smem + SM_GWS + j1*4);
            float2 b2p2 = *(float2*)(smem + SM_B2S + j2*4);
            float2 gwp2 = *(float2*)(smem + SM_GWS + j2*4);
            float v0 = fmaxf(acc[u*8+0] + b2p1.x, 0.f);
            float v1 = fmaxf(acc[u*8+1] + b2p1.y, 0.f);
            float v2 = fmaxf(acc[u*8+2] + b2p1.x, 0.f);
            float v3 = fmaxf(acc[u*8+3] + b2p1.y, 0.f);
            float v4 = fmaxf(acc[u*8+4] + b2p2.x, 0.f);
            float v5 = fmaxf(acc[u*8+5] + b2p2.y, 0.f);
            float v6 = fmaxf(acc[u*8+6] + b2p2.x, 0.f);
            float v7 = fmaxf(acc[u*8+7] + b2p2.y, 0.f);
            S1a += v0+v1+v4+v5;
            S2a = fmaf(v0,v0,fmaf(v1,v1,fmaf(v4,v4,fmaf(v5,v5,S2a))));
            Swa = fmaf(gwp1.x,v0,fmaf(gwp1.y,v1,fmaf(gwp2.x,v4,fmaf(gwp2.y,v5,Swa))));
            S1b += v2+v3+v6+v7;
            S2b = fmaf(v2,v2,fmaf(v3,v3,fmaf(v6,v6,fmaf(v7,v7,S2b))));
            Swb = fmaf(gwp1.x,v2,fmaf(gwp1.y,v3,fmaf(gwp2.x,v6,fmaf(gwp2.y,v7,Swb))));
        }
#pragma unroll
        for (int o = 1; o <= 2; o <<= 1) {
            S1a += __shfl_xor_sync(0xffffffffu, S1a, o);
            S2a += __shfl_xor_sync(0xffffffffu, S2a, o);
            Swa += __shfl_xor_sync(0xffffffffu, Swa, o);
            S1b += __shfl_xor_sync(0xffffffffu, S1b, o);
            S2b += __shfl_xor_sync(0xffffffffu, S2b, o);
            Swb += __shfl_xor_sync(0xffffffffu, Swb, o);
        }
        const int rA = 16*wm + (lane >> 2);
        if ((lane & 3) == 0 && nhalf == 1) {
            epi1[rA] = S1a; epi2[rA] = S2a; epiw[rA] = Swa;
            epi1[rA+8] = S1b; epi2[rA+8] = S2b; epiw[rA+8] = Swb;
        }
        __syncthreads();   // also the iteration barrier
        if ((lane & 3) == 0 && nhalf == 0) {
            const float Sgw = smf[SM_SCAL/4 + 0], Sbw = smf[SM_SCAL/4 + 1];
            const int offr = (r_ * (r_ - 1)) / 2 - OFFBASE + src0;
            {
                const float S1t = S1a + epi1[rA];
                const float S2t = S2a + epi2[rA];
                const float Swt = Swa + epiw[rA];
                const float mu2 = S1t * (1.f/128.f);
                const float var2 = S2t * (1.f/128.f) - mu2 * mu2;
                const float rs2 = rsqrtf(var2 + 1e-5f);
                if (rA < nvalid)
                    g_logits[b_ * EEDGES + offr + rA] = rs2 * (Swt - mu2 * Sgw) + Sbw;
            }
            {
                const int rB = rA + 8;
                const float S1t = S1b + epi1[rB];
                const float S2t = S2b + epi2[rB];
                const float Swt = Swb + epiw[rB];
                const float mu2 = S1t * (1.f/128.f);
                const float var2 = S2t * (1.f/128.f) - mu2 * mu2;
                const float rs2 = rsqrtf(var2 + 1e-5f);
                if (rB < nvalid)
                    g_logits[b_ * EEDGES + offr + rB] = rs2 * (Swt - mu2 * Sgw) + Sbw;
            }
        }
    }
}

// ---------------- K3a: gumbel + partial argmax ------------------------------
__global__ void k_gumbel_part() {
    const int c = blockIdx.x;
    const int bs = blockIdx.y;
    const int b = bs / NSAMP;
    const int tid = threadIdx.x;
    const float* lg = g_logits + b * EEDGES;

    float bz = __int_as_float(0xff800000);
    int bestE = 0x7fffffff;

    for (int t = tid; t < CHSZ; t += 256) {
        const u32 e = (u32)(c * CHSZ + t);
        const u32 i = (u32)bs * (u32)EEDGES + e;
        float z = lg[e] + bits_to_gumbel(tf_xor(0u, i));
        if (z > bz || (z == bz && (int)e < bestE)) { bz = z; bestE = (int)e; }
    }

    __shared__ float zs[256];
    __shared__ int   es[256];
    zs[tid] = bz; es[tid] = bestE;
    __syncthreads();
    for (int st = 128; st; st >>= 1) {
        if (tid < st) {
            if (zs[tid + st] > zs[tid] ||
                (zs[tid + st] == zs[tid] && es[tid + st] < es[tid])) {
                zs[tid] = zs[tid + st]; es[tid] = es[tid + st];
            }
        }
        __syncthreads();
    }
    if (tid == 0) { g_partZ[bs * NCHUNK + c] = zs[0]; g_partE[bs * NCHUNK + c] = es[0]; }
}

// ---------------- K3b+K4: final argmax + scatter -----------------------------
__global__ void k_final_scatter(float* __restrict__ out) {
    const int t = threadIdx.x;
    if (t >= NBS) return;
    float bz = __int_as_float(0xff800000);
    int bestE = 0;
    for (int c = 0; c < NCHUNK; c++) {
        float z = g_partZ[t * NCHUNK + c];
        int   e = g_partE[t * NCHUNK + c];
        if (z > bz || (z == bz && e < bestE)) { bz = z; bestE = e; }
    }
    const int v = bestE + OFFBASE;
    int r = (int)((1.0 + sqrt(8.0 * (double)v + 1.0)) * 0.5);
    while (r * (r - 1) / 2 > v) r--;
    while (r * (r + 1) / 2 <= v) r++;
    const int src = v - r * (r - 1) / 2;
    const int b = t / NSAMP;
    out[(size_t)b * NNODES * NNODES + r * NNODES + src] = 1.0f;
}

// ---------------- launch -----------------------------------------------------
extern "C" void kernel_launch(void* const* d_in, const int* in_sizes, int n_in,
                              void* d_out, int out_size) {
    const float* nodes = (const float*)d_in[0];
    const float* W1  = (const float*)d_in[1];
    const float* b1  = (const float*)d_in[2];
    const float* g1  = (const float*)d_in[3];
    const float* be1 = (const float*)d_in[4];
    const float* W2  = (const float*)d_in[5];
    const float* b2  = (const float*)d_in[6];
    const float* g2  = (const float*)d_in[7];
    const float* be2 = (const float*)d_in[8];
    const float* W3  = (const float*)d_in[9];
    float* out = (float*)d_out;

    cudaMemsetAsync(out, 0, (size_t)out_size * sizeof(float), 0);

    k_proj<<<(BATCH * NNODES) / 4, 256>>>(nodes, W1);
    k_wprep<<<64, 256>>>(W2);

    cudaFuncSetAttribute(k_edge_mma, cudaFuncAttributeMaxDynamicSharedMemorySize,
                         SMEM_TOTAL);
    k_edge_mma<<<NCTA, 256, SMEM_TOTAL>>>(b1, g1, be1, b2, g2, be2, W3);

    dim3 gg(NCHUNK, NBS);
    k_gumbel_part<<<gg, 256>>>();
    k_final_scatter<<<1, 32>>>(out);
}

// round 13
// speedup vs baseline: 1.2266x; 1.1055x over previous
#include <cuda_runtime.h>
#include <cuda_bf16.h>
#include <cstdint>
#include <cstring>

// ---------------- problem constants ----------------
#define FEAT     128
#define NNODES   512
#define BATCH    4
#define NSAMP    5
#define EEDGES   97920
#define OFFBASE  32896
#define NCHUNK   48
#define CHSZ     2040
#define NBS      (BATCH*NSAMP)
#define NVTILES  3568          // valid M=128 tiles: 4 * (128*3 + 127*4)
#define NCTA     148

typedef unsigned long long ull;
typedef unsigned int u32;

// ---------------- device scratch ----------------
__device__ float g_projA[BATCH*NNODES*FEAT];
__device__ float g_projB[BATCH*NNODES*FEAT];
__device__ float g_logits[BATCH*EEDGES];
__device__ float g_partZ[NBS*NCHUNK];
__device__ int   g_partE[NBS*NCHUNK];
__device__ __align__(16) unsigned char g_Wimg[65536];  // Whi(32K), Wlo(32K): Wt[n][k] swizzled

// ---------------- smem layout (bytes) ----------------
#define SM_WHI   0        // 32768
#define SM_WLO   32768    // 32768
#define SM_AHI   65536    // 32768 (128 rows x 256B)
#define SM_ALO   98304    // 32768
#define SM_AROW  131072   // [2][128] f32
#define SM_B1S   132096
#define SM_G1S   132608
#define SM_BE1S  133120
#define SM_B2S   133632
#define SM_GWS   134144
#define SM_EPI1  134656   // [128] f32
#define SM_EPI2  135168
#define SM_EPIW  135680
#define SM_SCAL  136192
#define SMEM_TOTAL 136224

static __device__ __forceinline__ u32 smem_u32(const void* p) {
    u32 a;
    asm("{ .reg .u64 t; cvta.to.shared.u64 t, %1; cvt.u32.u64 %0, t; }" : "=r"(a) : "l"(p));
    return a;
}

#define LDSM4(r0,r1,r2,r3,addr) \
  asm volatile("ldmatrix.sync.aligned.m8n8.x4.shared.b16 {%0,%1,%2,%3}, [%4];" \
    : "=r"(r0),"=r"(r1),"=r"(r2),"=r"(r3) : "r"(addr))

#define MMA16816(d, a0,a1,a2,a3, b0,b1) \
  asm volatile("mma.sync.aligned.m16n8k16.row.col.f32.bf16.bf16.f32 " \
    "{%0,%1,%2,%3}, {%4,%5,%6,%7}, {%8,%9}, {%0,%1,%2,%3};" \
    : "+f"((d)[0]),"+f"((d)[1]),"+f"((d)[2]),"+f"((d)[3]) \
    : "r"(a0),"r"(a1),"r"(a2),"r"(a3), "r"(b0),"r"(b1))

// ---------------- Threefry / gumbel ----------------
#define TF_ROUND(r) { x0 += x1; x1 = (x1 << (r)) | (x1 >> (32 - (r))); x1 ^= x0; }
static __device__ __forceinline__ u32 tf_xor(u32 x0, u32 x1) {
    const u32 k0 = 0u, k1 = 42u;
    const u32 ks2 = 0x1BD11BDAu ^ k0 ^ k1;
    x0 += k0; x1 += k1;
    TF_ROUND(13) TF_ROUND(15) TF_ROUND(26) TF_ROUND(6)
    x0 += k1; x1 += ks2 + 1u;
    TF_ROUND(17) TF_ROUND(29) TF_ROUND(16) TF_ROUND(24)
    x0 += ks2; x1 += k0 + 2u;
    TF_ROUND(13) TF_ROUND(15) TF_ROUND(26) TF_ROUND(6)
    x0 += k0; x1 += k1 + 3u;
    TF_ROUND(17) TF_ROUND(29) TF_ROUND(16) TF_ROUND(24)
    x0 += k1; x1 += ks2 + 4u;
    TF_ROUND(13) TF_ROUND(15) TF_ROUND(26) TF_ROUND(6)
    x0 += ks2; x1 += k0 + 5u;
    return x0 ^ x1;
}
static __device__ __forceinline__ float bits_to_gumbel(u32 bits) {
    float f = __uint_as_float((bits >> 9) | 0x3f800000u) - 1.0f;
    float u = fmaxf(f, 1.17549435e-38f);
    return -logf(-logf(u));
}

// valid-tile decode (M=128): per batch 892 (r 257..384: 3 chunks, 385..511: 4)
static __device__ __forceinline__ void tile_decode(int t, int& b, int& r, int& c) {
    b = t / 892;
    int idx = t - b * 892;
    if (idx < 384) { int d = idx / 3; r = 257 + d; c = idx - d * 3; }
    else { int i2 = idx - 384; r = 385 + (i2 >> 2); c = i2 & 3; }
}

// ---------------- K1: per-node projections ----------------------------------
__global__ void k_proj(const float* __restrict__ nodes, const float* __restrict__ W1) {
    __shared__ float nrow[4][FEAT];
    const int tid = threadIdx.x, blk = blockIdx.x;
    const float* src = nodes + (size_t)blk * 4 * FEAT;
    for (int i = tid; i < 4 * FEAT; i += 256) ((float*)nrow)[i] = src[i];
    __syncthreads();
    const int half = tid >> 7, o = tid & 127;
    const float* w = W1 + half * FEAT * FEAT + o;
    float a0 = 0.f, a1 = 0.f, a2 = 0.f, a3 = 0.f;
#pragma unroll 8
    for (int k = 0; k < FEAT; k++) {
        float wv = w[k * FEAT];
        a0 = fmaf(nrow[0][k], wv, a0);
        a1 = fmaf(nrow[1][k], wv, a1);
        a2 = fmaf(nrow[2][k], wv, a2);
        a3 = fmaf(nrow[3][k], wv, a3);
    }
    float* dst = half ? g_projB : g_projA;
    int base = blk * 4 * FEAT + o;
    dst[base] = a0; dst[base + FEAT] = a1;
    dst[base + 2 * FEAT] = a2; dst[base + 3 * FEAT] = a3;
}

// ---------------- K1b: W2 -> bf16 hi/lo Wt[n][k] swizzled image --------------
__global__ void k_wprep(const float* __restrict__ W2) {
    const int idx = blockIdx.x * 256 + threadIdx.x;   // 0..16383
    const int k = idx >> 7, n = idx & 127;
    const float w = W2[k * FEAT + n];
    __nv_bfloat16 hb = __float2bfloat16(w);
    float lo = w - __bfloat162float(hb);
    __nv_bfloat16 lb = __float2bfloat16(lo);
    const u32 off = (u32)(n * 256) + (((u32)(k * 2)) ^ ((u32)(n & 7) << 4));
    unsigned short hbits, lbits;
    memcpy(&hbits, &hb, 2); memcpy(&lbits, &lb, 2);
    *(unsigned short*)(g_Wimg + off) = hbits;
    *(unsigned short*)(g_Wimg + 32768 + off) = lbits;
}

// ---------------- dummy: positions k_edge as 4th launch for ncu --------------
__global__ void k_dummy() {}

// ---------------- K2: persistent mma.sync edge-MLP (M128, 4Mx2N warps) -------
__global__ void __launch_bounds__(256, 1)
k_edge_mma(const float* __restrict__ b1, const float* __restrict__ g1,
           const float* __restrict__ be1, const float* __restrict__ b2,
           const float* __restrict__ g2, const float* __restrict__ be2,
           const float* __restrict__ W3) {
    extern __shared__ __align__(1024) char smem[];
    const u32 sb = smem_u32(smem);
    float* smf = (float*)smem;
    const int tid = threadIdx.x;
    const int lane = tid & 31, w = tid >> 5;

    // ---- one-time init ----
    {
        const uint4* src = (const uint4*)g_Wimg;
        uint4* dst = (uint4*)smem;
        for (int i = tid; i < 4096; i += 256) dst[i] = src[i];
    }
    if (tid < 128) {
        smf[SM_B1S/4 + tid]  = b1[tid];
        smf[SM_G1S/4 + tid]  = g1[tid];
        smf[SM_BE1S/4 + tid] = be1[tid];
        smf[SM_B2S/4 + tid]  = b2[tid];
        smf[SM_GWS/4 + tid]  = g2[tid] * W3[tid];
    }
    __syncthreads();
    if (tid == 0) {
        float sg = 0.f, sbw = 0.f;
        for (int j = 0; j < 128; j++) {
            sg  += smf[SM_GWS/4 + j];
            sbw += be2[j] * W3[j];
        }
        smf[SM_SCAL/4 + 0] = sg;
        smf[SM_SCAL/4 + 1] = sbw;
    }
    __syncthreads();

    const float* g1s  = smf + SM_G1S/4;
    const float* be1s = smf + SM_BE1S/4;
    float* arow = smf + SM_AROW/4;     // [2][128]
    float* epi1 = smf + SM_EPI1/4;
    float* epi2 = smf + SM_EPI2/4;
    float* epiw = smf + SM_EPIW/4;

    // phase-1 geometry: thread = (row m 0..127, half h); partner lane = lane^1
    const int m = tid >> 1, h = tid & 1;
    const u32 mswz = (u32)(m & 7) << 4;

    // GEMM geometry: 8 warps = 4 M-warps (M32) x 2 N-halves (N64)
    const int wm = w & 3, nhalf = w >> 2;
    const u32 swz = (u32)(lane & 7) << 4;
    const u32 a_rowoff = (u32)(wm*32 + (lane & 7) + ((lane >> 3) & 1) * 8) * 256;
    const u32 akc = (u32)((lane >> 4) & 1) * 16;
    const u32 b_rowin = (u32)(((lane >> 4) & 1) * 8 + (lane & 7)) * 256 + (u32)nhalf * 16384;
    const u32 bkc = (u32)((lane >> 3) & 1) * 16;
    const u32 aHIb = sb + SM_AHI + a_rowoff;
    const u32 aLOb = sb + SM_ALO + a_rowoff;
    const u32 wHIb = sb + SM_WHI + b_rowin;
    const u32 wLOb = sb + SM_WLO + b_rowin;

    // ---- initial arow prefetch (tile t0) ----
    int t = blockIdx.x;
    if (t < NVTILES) {
        int b_, r_, c_; tile_decode(t, b_, r_, c_);
        if (tid < 128)
            arow[tid] = g_projA[(((size_t)(b_ << 9) + r_) << 7) + tid] + smf[SM_B1S/4 + tid];
    }
    __syncthreads();

    int pc = 0;
    for (; t < NVTILES; t += NCTA, pc++) {
        int b_, r_, c_; tile_decode(t, b_, r_, c_);
        const int src0 = c_ << 7;
        const int nvalid = min(128, r_ - src0);
        const int par = pc & 1;
        const float* ar = arow + par * 128 + h * 64;

        // ---- phase 1: relu + LN stats (half-row per thread) ----
        const bool valid = m < nvalid;
        float x[64];
        float S1p = 0.f, S2p = 0.f;
        if (valid) {
            const float4* bp = (const float4*)(g_projB + (((size_t)(b_ << 9) + src0 + m) << 7) + h * 64);
#pragma unroll
            for (int i = 0; i < 16; i++) {
                float4 v4 = bp[i];
                const int j0 = i * 4;
                x[j0+0] = fmaxf(ar[j0+0] + v4.x, 0.f);
                x[j0+1] = fmaxf(ar[j0+1] + v4.y, 0.f);
                x[j0+2] = fmaxf(ar[j0+2] + v4.z, 0.f);
                x[j0+3] = fmaxf(ar[j0+3] + v4.w, 0.f);
                S1p += x[j0+0] + x[j0+1] + x[j0+2] + x[j0+3];
                S2p = fmaf(x[j0+0], x[j0+0], S2p); S2p = fmaf(x[j0+1], x[j0+1], S2p);
                S2p = fmaf(x[j0+2], x[j0+2], S2p); S2p = fmaf(x[j0+3], x[j0+3], S2p);
            }
        } else {
#pragma unroll
            for (int i = 0; i < 64; i++) x[i] = 0.f;
        }
        S1p += __shfl_xor_sync(0xffffffffu, S1p, 1);
        S2p += __shfl_xor_sync(0xffffffffu, S2p, 1);
        const float mu = S1p * (1.f/128.f);
        const float var = S2p * (1.f/128.f) - mu * mu;
        const float rstd = rsqrtf(var + 1e-5f);

        // convert + store A tiles (hi/lo): 8 uint4 per buffer
#pragma unroll
        for (int i = 0; i < 8; i++) {
            u32 hu[4], lu[4];
#pragma unroll
            for (int pp = 0; pp < 4; pp++) {
                const int jl = i*8 + pp*2;
                const int j  = h*64 + jl;
                float y0 = 0.f, y1 = 0.f;
                if (valid) {
                    y0 = fmaf((x[jl]   - mu) * rstd, g1s[j],   be1s[j]);
                    y1 = fmaf((x[jl+1] - mu) * rstd, g1s[j+1], be1s[j+1]);
                }
                __nv_bfloat162 hb = __floats2bfloat162_rn(y0, y1);
                float r0 = y0 - __bfloat162float(hb.x);
                float r1 = y1 - __bfloat162float(hb.y);
                __nv_bfloat162 lb = __floats2bfloat162_rn(r0, r1);
                memcpy(&hu[pp], &hb, 4); memcpy(&lu[pp], &lb, 4);
            }
            const u32 off = (u32)(m * 256) + (((u32)(h*128 + i*16)) ^ mswz);
            *(uint4*)(smem + SM_AHI + off) = make_uint4(hu[0], hu[1], hu[2], hu[3]);
            *(uint4*)(smem + SM_ALO + off) = make_uint4(lu[0], lu[1], lu[2], lu[3]);
        }

        // ---- prefetch next tile's arow (overlaps with GEMM) ----
        {
            const int tn = t + NCTA;
            if (tn < NVTILES && tid < 128) {
                int bn, rn, cn; tile_decode(tn, bn, rn, cn);
                arow[(par ^ 1) * 128 + tid] =
                    g_projA[(((size_t)(bn << 9) + rn) << 7) + tid] + smf[SM_B1S/4 + tid];
            }
        }
        __syncthreads();   // A tiles ready

        // ---- GEMM: D = Ahi*Whi + Alo*Whi + Ahi*Wlo; warp = M32 x N64 ----
        float acc[2][32];
#pragma unroll
        for (int mf = 0; mf < 2; mf++)
#pragma unroll
            for (int i = 0; i < 32; i++) acc[mf][i] = 0.f;

#pragma unroll
        for (int s = 0; s < 8; s++) {
            const u32 aoff = ((u32)(s*32) + akc) ^ swz;
            const u32 boff = ((u32)(s*32) + bkc) ^ swz;
            u32 ah[2][4], al[2][4];
            LDSM4(ah[0][0],ah[0][1],ah[0][2],ah[0][3], aHIb + aoff);
            LDSM4(ah[1][0],ah[1][1],ah[1][2],ah[1][3], aHIb + 4096 + aoff);
            LDSM4(al[0][0],al[0][1],al[0][2],al[0][3], aLOb + aoff);
            LDSM4(al[1][0],al[1][1],al[1][2],al[1][3], aLOb + 4096 + aoff);
#pragma unroll
            for (int u = 0; u < 4; u++) {
                u32 bh0,bh1,bh2,bh3, bl0,bl1,bl2,bl3;
                LDSM4(bh0,bh1,bh2,bh3, wHIb + (u32)(u*4096) + boff);
                LDSM4(bl0,bl1,bl2,bl3, wLOb + (u32)(u*4096) + boff);
#pragma unroll
                for (int mf = 0; mf < 2; mf++) {
                    MMA16816(acc[mf] + u*8,     ah[mf][0],ah[mf][1],ah[mf][2],ah[mf][3], bh0,bh1);
                    MMA16816(acc[mf] + u*8 + 4, ah[mf][0],ah[mf][1],ah[mf][2],ah[mf][3], bh2,bh3);
                    MMA16816(acc[mf] + u*8,     al[mf][0],al[mf][1],al[mf][2],al[mf][3], bh0,bh1);
                    MMA16816(acc[mf] + u*8 + 4, al[mf][0],al[mf][1],al[mf][2],al[mf][3], bh2,bh3);
                    MMA16816(acc[mf] + u*8,     ah[mf][0],ah[mf][1],ah[mf][2],ah[mf][3], bl0,bl1);
                    MMA16816(acc[mf] + u*8 + 4, ah[mf][0],ah[mf][1],ah[mf][2],ah[mf][3], bl2,bl3);
                }
            }
        }

        // ---- epilogue: relu + LN stats + W3 dot over this warp's N64 ----
        const int tq = (lane & 3) * 2;
        const int nb = nhalf * 64;
        float S1[2][2], S2[2][2], Sw[2][2];
#pragma unroll
        for (int mf = 0; mf < 2; mf++) {
            float s1a=0.f,s2a=0.f,swa=0.f, s1b=0.f,s2b=0.f,swb=0.f;
#pragma unroll
            for (int u = 0; u < 4; u++) {
                const int j1 = nb + u*16 + tq;
                const int j2 = j1 + 8;
                float2 b2p1 = *(float2*)(smem + SM_B2S + j1*4);
                float2 gwp1 = *(float2*)(smem + SM_GWS + j1*4);
                float2 b2p2 = *(float2*)(smem + SM_B2S + j2*4);
                float2 gwp2 = *(float2*)(smem + SM_GWS + j2*4);
                float v0 = fmaxf(acc[mf][u*8+0] + b2p1.x, 0.f);
                float v1 = fmaxf(acc[mf][u*8+1] + b2p1.y, 0.f);
                float v2 = fmaxf(acc[mf][u*8+2] + b2p1.x, 0.f);
                float v3 = fmaxf(acc[mf][u*8+3] + b2p1.y, 0.f);
                float v4 = fmaxf(acc[mf][u*8+4] + b2p2.x, 0.f);
                float v5 = fmaxf(acc[mf][u*8+5] + b2p2.y, 0.f);
                float v6 = fmaxf(acc[mf][u*8+6] + b2p2.x, 0.f);
                float v7 = fmaxf(acc[mf][u*8+7] + b2p2.y, 0.f);
                s1a += v0+v1+v4+v5;
                s2a = fmaf(v0,v0,fmaf(v1,v1,fmaf(v4,v4,fmaf(v5,v5,s2a))));
                swa = fmaf(gwp1.x,v0,fmaf(gwp1.y,v1,fmaf(gwp2.x,v4,fmaf(gwp2.y,v5,swa))));
                s1b += v2+v3+v6+v7;
                s2b = fmaf(v2,v2,fmaf(v3,v3,fmaf(v6,v6,fmaf(v7,v7,s2b))));
                swb = fmaf(gwp1.x,v2,fmaf(gwp1.y,v3,fmaf(gwp2.x,v6,fmaf(gwp2.y,v7,swb))));
            }
#pragma unroll
            for (int o = 1; o <= 2; o <<= 1) {
                s1a += __shfl_xor_sync(0xffffffffu, s1a, o);
                s2a += __shfl_xor_sync(0xffffffffu, s2a, o);
                swa += __shfl_xor_sync(0xffffffffu, swa, o);
                s1b += __shfl_xor_sync(0xffffffffu, s1b, o);
                s2b += __shfl_xor_sync(0xffffffffu, s2b, o);
                swb += __shfl_xor_sync(0xffffffffu, swb, o);
            }
            S1[mf][0]=s1a; S2[mf][0]=s2a; Sw[mf][0]=swa;
            S1[mf][1]=s1b; S2[mf][1]=s2b; Sw[mf][1]=swb;
        }
        if ((lane & 3) == 0 && nhalf == 1) {
#pragma unroll
            for (int mf = 0; mf < 2; mf++) {
                const int r0 = wm*32 + mf*16 + (lane >> 2);
                epi1[r0] = S1[mf][0]; epi2[r0] = S2[mf][0]; epiw[r0] = Sw[mf][0];
                epi1[r0+8] = S1[mf][1]; epi2[r0+8] = S2[mf][1]; epiw[r0+8] = Sw[mf][1];
            }
        }
        __syncthreads();   // also the iteration barrier
        if ((lane & 3) == 0 && nhalf == 0) {
            const float Sgw = smf[SM_SCAL/4 + 0], Sbw = smf[SM_SCAL/4 + 1];
            const int offr = (r_ * (r_ - 1)) / 2 - OFFBASE + src0;
#pragma unroll
            for (int mf = 0; mf < 2; mf++) {
#pragma unroll
                for (int hh = 0; hh < 2; hh++) {
                    const int row = wm*32 + mf*16 + (lane >> 2) + hh*8;
                    const float S1t = S1[mf][hh] + epi1[row];
                    const float S2t = S2[mf][hh] + epi2[row];
                    const float Swt = Sw[mf][hh] + epiw[row];
                    const float mu2 = S1t * (1.f/128.f);
                    const float var2 = S2t * (1.f/128.f) - mu2 * mu2;
                    const float rs2 = rsqrtf(var2 + 1e-5f);
                    if (row < nvalid)
                        g_logits[b_ * EEDGES + offr + row] = rs2 * (Swt - mu2 * Sgw) + Sbw;
                }
            }
        }
    }
}

// ---------------- K3a: gumbel + partial argmax ------------------------------
__global__ void k_gumbel_part() {
    const int c = blockIdx.x;
    const int bs = blockIdx.y;
    const int b = bs / NSAMP;
    const int tid = threadIdx.x;
    const float* lg = g_logits + b * EEDGES;

    float bz = __int_as_float(0xff800000);
    int bestE = 0x7fffffff;

    for (int t = tid; t < CHSZ; t += 256) {
        const u32 e = (u32)(c * CHSZ + t);
        const u32 i = (u32)bs * (u32)EEDGES + e;
        float z = lg[e] + bits_to_gumbel(tf_xor(0u, i));
        if (z > bz || (z == bz && (int)e < bestE)) { bz = z; bestE = (int)e; }
    }

    __shared__ float zs[256];
    __shared__ int   es[256];
    zs[tid] = bz; es[tid] = bestE;
    __syncthreads();
    for (int st = 128; st; st >>= 1) {
        if (tid < st) {
            if (zs[tid + st] > zs[tid] ||
                (zs[tid + st] == zs[tid] && es[tid + st] < es[tid])) {
                zs[tid] = zs[tid + st]; es[tid] = es[tid + st];
            }
        }
        __syncthreads();
    }
    if (tid == 0) { g_partZ[bs * NCHUNK + c] = zs[0]; g_partE[bs * NCHUNK + c] = es[0]; }
}

// ---------------- K3b+K4: final argmax + scatter -----------------------------
__global__ void k_final_scatter(float* __restrict__ out) {
    const int t = threadIdx.x;
    if (t >= NBS) return;
    float bz = __int_as_float(0xff800000);
    int bestE = 0;
    for (int c = 0; c < NCHUNK; c++) {
        float z = g_partZ[t * NCHUNK + c];
        int   e = g_partE[t * NCHUNK + c];
        if (z > bz || (z == bz && e < bestE)) { bz = z; bestE = e; }
    }
    const int v = bestE + OFFBASE;
    int r = (int)((1.0 + sqrt(8.0 * (double)v + 1.0)) * 0.5);
    while (r * (r - 1) / 2 > v) r--;
    while (r * (r + 1) / 2 <= v) r++;
    const int src = v - r * (r - 1) / 2;
    const int b = t / NSAMP;
    out[(size_t)b * NNODES * NNODES + r * NNODES + src] = 1.0f;
}

// ---------------- launch -----------------------------------------------------
extern "C" void kernel_launch(void* const* d_in, const int* in_sizes, int n_in,
                              void* d_out, int out_size) {
    const float* nodes = (const float*)d_in[0];
    const float* W1  = (const float*)d_in[1];
    const float* b1  = (const float*)d_in[2];
    const float* g1  = (const float*)d_in[3];
    const float* be1 = (const float*)d_in[4];
    const float* W2  = (const float*)d_in[5];
    const float* b2  = (const float*)d_in[6];
    const float* g2  = (const float*)d_in[7];
    const float* be2 = (const float*)d_in[8];
    const float* W3  = (const float*)d_in[9];
    float* out = (float*)d_out;

    cudaMemsetAsync(out, 0, (size_t)out_size * sizeof(float), 0);

    k_proj<<<(BATCH * NNODES) / 4, 256>>>(nodes, W1);
    k_wprep<<<64, 256>>>(W2);
    k_dummy<<<1, 32>>>();   // positions k_edge_mma as the 4th launch for ncu

    cudaFuncSetAttribute(k_edge_mma, cudaFuncAttributeMaxDynamicSharedMemorySize,
                         SMEM_TOTAL);
    k_edge_mma<<<NCTA, 256, SMEM_TOTAL>>>(b1, g1, be1, b2, g2, be2, W3);

    dim3 gg(NCHUNK, NBS);
    k_gumbel_part<<<gg, 256>>>();
    k_final_scatter<<<1, 32>>>(out);
}